// round 1
// baseline (speedup 1.0000x reference)
#include <cuda_runtime.h>

#define N_NODES   1000000
#define N_EDGES   2000000
#define N_GRAPHS  50000
#define X_DIM     5
#define HIDDEN    110
#define G_DIM     5
#define BN_EPS    1e-5f

// ---------------- device scratch (no allocations allowed) ----------------
__device__ float  g_msg[N_NODES];          // per-node edge-message sum
__device__ double g_sumx[X_DIM];
__device__ double g_sumx2[X_DIM];
__device__ double g_sume;
__device__ double g_sume2;

struct Consts {
    float A[5][5];    // diag(s_x) @ (W_gnn @ W1)
    float cvec[5];    // t_x @ M1 + b_gnn @ W1 + b1
    float we1[5];     // W_e @ W1
    float W2[5][5];
    float b2[5];
    float s_e, t_e;   // folded edge BN affine
};
__device__ Consts g_c;

// ---------------- kernel 1: zero scratch + output ----------------
__global__ void zero_kernel(float* __restrict__ out) {
    int i      = blockIdx.x * blockDim.x + threadIdx.x;
    int stride = gridDim.x * blockDim.x;
    for (int k = i; k < N_NODES; k += stride) g_msg[k] = 0.f;
    for (int k = i; k < N_GRAPHS * G_DIM; k += stride) out[k] = 0.f;
    if (i < X_DIM) { g_sumx[i] = 0.0; g_sumx2[i] = 0.0; }
    if (i == X_DIM) { g_sume = 0.0; g_sume2 = 0.0; }
}

// ---------------- kernel 2: fused BN statistics for x and edge_attr ----------------
__global__ void stats_kernel(const float* __restrict__ x,
                             const float* __restrict__ ea) {
    float sx[5]  = {0.f, 0.f, 0.f, 0.f, 0.f};
    float sx2[5] = {0.f, 0.f, 0.f, 0.f, 0.f};
    int stride = gridDim.x * blockDim.x;
    int tid0   = blockIdx.x * blockDim.x + threadIdx.x;

    for (int n = tid0; n < N_NODES; n += stride) {
#pragma unroll
        for (int j = 0; j < 5; j++) {
            float v = x[n * 5 + j];
            sx[j]  += v;
            sx2[j] += v * v;
        }
    }

    float se = 0.f, se2 = 0.f;
    const float4* e4 = (const float4*)ea;
    for (int i = tid0; i < N_EDGES / 4; i += stride) {
        float4 v = e4[i];
        se  += v.x + v.y + v.z + v.w;
        se2 += v.x * v.x + v.y * v.y + v.z * v.z + v.w * v.w;
    }

    // warp reduce all 12 partials
#pragma unroll
    for (int off = 16; off > 0; off >>= 1) {
#pragma unroll
        for (int j = 0; j < 5; j++) {
            sx[j]  += __shfl_down_sync(0xffffffffu, sx[j],  off);
            sx2[j] += __shfl_down_sync(0xffffffffu, sx2[j], off);
        }
        se  += __shfl_down_sync(0xffffffffu, se,  off);
        se2 += __shfl_down_sync(0xffffffffu, se2, off);
    }

    __shared__ float red[12][8];   // [value][warp], blockDim<=256 -> 8 warps
    int w = threadIdx.x >> 5, l = threadIdx.x & 31;
    if (l == 0) {
#pragma unroll
        for (int j = 0; j < 5; j++) { red[j][w] = sx[j]; red[5 + j][w] = sx2[j]; }
        red[10][w] = se; red[11][w] = se2;
    }
    __syncthreads();
    if (threadIdx.x < 12) {
        float a = 0.f;
        int nw = blockDim.x >> 5;
        for (int k = 0; k < nw; k++) a += red[threadIdx.x][k];
        if (threadIdx.x < 5)       atomicAdd(&g_sumx[threadIdx.x], (double)a);
        else if (threadIdx.x < 10) atomicAdd(&g_sumx2[threadIdx.x - 5], (double)a);
        else if (threadIdx.x == 10) atomicAdd(&g_sume,  (double)a);
        else                        atomicAdd(&g_sume2, (double)a);
    }
}

// ---------------- kernel 3: fold weights + BN into tiny per-node affine ----------------
__global__ void consts_kernel(const float* __restrict__ W_gnn,
                              const float* __restrict__ b_gnn,
                              const float* __restrict__ W_e,
                              const float* __restrict__ W1,
                              const float* __restrict__ b1,
                              const float* __restrict__ W2,
                              const float* __restrict__ b2,
                              const float* __restrict__ bn_x_g,
                              const float* __restrict__ bn_x_b,
                              const float* __restrict__ bn_e_g,
                              const float* __restrict__ bn_e_b) {
    __shared__ float M1[5][5], we1[5], bg1[5];
    int tid = threadIdx.x;
    if (tid < 25) {
        int j = tid / 5, g = tid % 5;
        float acc = 0.f;
        for (int k = 0; k < HIDDEN; k++) acc += W_gnn[j * HIDDEN + k] * W1[k * 5 + g];
        M1[j][g] = acc;
    } else if (tid < 30) {
        int g = tid - 25;
        float acc = 0.f;
        for (int k = 0; k < HIDDEN; k++) acc += W_e[k] * W1[k * 5 + g];
        we1[g] = acc;
    } else if (tid < 35) {
        int g = tid - 30;
        float acc = 0.f;
        for (int k = 0; k < HIDDEN; k++) acc += b_gnn[k] * W1[k * 5 + g];
        bg1[g] = acc + b1[g];
    }
    __syncthreads();
    if (tid == 0) {
        float s_x[5], t_x[5];
        for (int j = 0; j < 5; j++) {
            double mu  = g_sumx[j] / (double)N_NODES;
            double var = g_sumx2[j] / (double)N_NODES - mu * mu;
            float  s   = bn_x_g[j] * rsqrtf((float)var + BN_EPS);
            s_x[j] = s;
            t_x[j] = bn_x_b[j] - (float)mu * s;
        }
        for (int j = 0; j < 5; j++)
            for (int g = 0; g < 5; g++)
                g_c.A[j][g] = s_x[j] * M1[j][g];
        for (int g = 0; g < 5; g++) {
            float c = bg1[g];
            for (int j = 0; j < 5; j++) c += t_x[j] * M1[j][g];
            g_c.cvec[g] = c;
            g_c.we1[g]  = we1[g];
            g_c.b2[g]   = b2[g];
            for (int g2 = 0; g2 < 5; g2++) g_c.W2[g][g2] = W2[g * 5 + g2];
        }
        double mue  = g_sume / (double)N_EDGES;
        double vare = g_sume2 / (double)N_EDGES - mue * mue;
        float  se   = bn_e_g[0] * rsqrtf((float)vare + BN_EPS);
        g_c.s_e = se;
        g_c.t_e = bn_e_b[0] - (float)mue * se;
    }
}

// ---------------- kernel 4: scatter normalized edge messages ----------------
__global__ void scatter_kernel(const float* __restrict__ ea,
                               const int*   __restrict__ dst) {
    int i = blockIdx.x * blockDim.x + threadIdx.x;
    if (i < N_EDGES) {
        float v = fmaf(g_c.s_e, ea[i], g_c.t_e);
        atomicAdd(&g_msg[dst[i]], v);
    }
}

// ---------------- kernel 5: per-node affine->swish->affine + sorted-segment pool ----------------
__global__ void main_kernel(const float* __restrict__ x,
                            const int*   __restrict__ batch,
                            float* __restrict__ out) {
    __shared__ Consts c;
    {
        const float* src = (const float*)&g_c;
        float* dstp = (float*)&c;
        for (int i = threadIdx.x; i < (int)(sizeof(Consts) / 4); i += blockDim.x)
            dstp[i] = src[i];
    }
    __syncthreads();

    int n = blockIdx.x * blockDim.x + threadIdx.x;
    float o[5] = {0.f, 0.f, 0.f, 0.f, 0.f};
    int b = -1;

    if (n < N_NODES) {
        float m = g_msg[n];
        float p[5];
#pragma unroll
        for (int g = 0; g < 5; g++) p[g] = fmaf(m, c.we1[g], c.cvec[g]);
#pragma unroll
        for (int j = 0; j < 5; j++) {
            float xv = x[n * 5 + j];
#pragma unroll
            for (int g = 0; g < 5; g++) p[g] = fmaf(xv, c.A[j][g], p[g]);
        }
#pragma unroll
        for (int g = 0; g < 5; g++) {
            float q = p[g] / (1.f + __expf(-p[g]));   // swish
#pragma unroll
            for (int g2 = 0; g2 < 5; g2++) o[g2] = fmaf(q, c.W2[g][g2], o[g2]);
        }
#pragma unroll
        for (int g2 = 0; g2 < 5; g2++) o[g2] += c.b2[g2];
        b = batch[n];
    }

    // batch is sorted -> warp-level segmented sum, only segment tails hit gmem atomics
    const unsigned FULL = 0xffffffffu;
    int lane = threadIdx.x & 31;
#pragma unroll
    for (int off = 1; off < 32; off <<= 1) {
        int   bo = __shfl_up_sync(FULL, b, off);
        float t0 = __shfl_up_sync(FULL, o[0], off);
        float t1 = __shfl_up_sync(FULL, o[1], off);
        float t2 = __shfl_up_sync(FULL, o[2], off);
        float t3 = __shfl_up_sync(FULL, o[3], off);
        float t4 = __shfl_up_sync(FULL, o[4], off);
        if (lane >= off && bo == b) {
            o[0] += t0; o[1] += t1; o[2] += t2; o[3] += t3; o[4] += t4;
        }
    }
    int bnext = __shfl_down_sync(FULL, b, 1);
    bool tail = (lane == 31) || (bnext != b);
    if (tail && n < N_NODES) {
#pragma unroll
        for (int g2 = 0; g2 < 5; g2++)
            atomicAdd(&out[b * 5 + g2], o[g2]);
    }
}

// ---------------- launch ----------------
extern "C" void kernel_launch(void* const* d_in, const int* in_sizes, int n_in,
                              void* d_out, int out_size) {
    const float* x      = (const float*)d_in[0];
    const float* ea     = (const float*)d_in[1];
    const int*   batch  = (const int*)  d_in[2];
    const int*   eidx   = (const int*)  d_in[3];
    const float* bn_x_g = (const float*)d_in[4];
    const float* bn_x_b = (const float*)d_in[5];
    const float* bn_e_g = (const float*)d_in[6];
    const float* bn_e_b = (const float*)d_in[7];
    const float* W_gnn  = (const float*)d_in[8];
    const float* b_gnn  = (const float*)d_in[9];
    const float* W_e    = (const float*)d_in[10];
    const float* W1     = (const float*)d_in[11];
    const float* b1     = (const float*)d_in[12];
    const float* W2     = (const float*)d_in[13];
    const float* b2     = (const float*)d_in[14];
    float* out = (float*)d_out;

    zero_kernel<<<2048, 256>>>(out);
    stats_kernel<<<1024, 256>>>(x, ea);
    consts_kernel<<<1, 64>>>(W_gnn, b_gnn, W_e, W1, b1, W2, b2,
                             bn_x_g, bn_x_b, bn_e_g, bn_e_b);
    scatter_kernel<<<(N_EDGES + 255) / 256, 256>>>(ea, eidx + N_EDGES);
    main_kernel<<<(N_NODES + 255) / 256, 256>>>(x, batch, out);
}